// round 6
// baseline (speedup 1.0000x reference)
#include <cuda_runtime.h>
#include <cstddef>

#define BB 16
#define SS 512
#define DD 384
#define K  4            // tokens per scatter block
#define NT 384          // K * 96 threads = 12 warps (3 per SMSP, balanced)

// Block-wide sum over 384 threads; every thread receives the total.
__device__ __forceinline__ int block_sum_384(int s) {
    const int lane = threadIdx.x & 31, warp = threadIdx.x >> 5;
    #pragma unroll
    for (int off = 16; off; off >>= 1) s += __shfl_down_sync(0xffffffffu, s, off);
    __shared__ int ws[12];
    if (lane == 0) ws[warp] = s;
    __syncthreads();
    int tot = 0;
    #pragma unroll
    for (int i = 0; i < 12; i++) tot += ws[i];
    return tot;
}

// One fused launch, three grid segments:
//   [0, 2048)               : scatter, 4 tokens per block (one 96-lane group each)
//   [2048, 2048+padBlocks)  : zero padding frames [total_b, L)
//   [2048+padBlocks]        : tail (appended out_lengths as float)
__global__ void __launch_bounds__(NT) fused_kernel(
    const float* __restrict__ hidden, const int* __restrict__ dur,
    float* __restrict__ out, int L, int padBlocks, int bpb, int tail_n) {
    const int tid = threadIdx.x;
    const int blk = blockIdx.x;
    const int SC = BB * SS / K;            // 2048 scatter blocks

    if (blk < SC) {
        // ---- scatter: tokens [base, base+K) of one batch ----
        const int base = blk * K;          // K divides SS -> same batch
        const int b = base >> 9;
        const int t0 = base & (SS - 1);
        const int* drow = dur + b * SS;

        int s = 0;
        for (int i = tid; i < t0; i += NT) s += drow[i];
        const int P = block_sum_384(s);    // exclusive prefix at t0

        const int g  = tid / 96;           // token group 0..3
        const int gi = tid - g * 96;       // float4 lane within frame
        const int t  = t0 + g;
        const int d  = drow[t];
        if (d == 0) return;

        int excl = P;
        #pragma unroll
        for (int j = 0; j < K - 1; j++)
            if (j < g) excl += drow[t0 + j];   // <=3 L1-hit loads

        const float4 v = reinterpret_cast<const float4*>(
            hidden + (size_t)(b * SS + t) * DD)[gi];
        float4* op = reinterpret_cast<float4*>(
            out + ((size_t)b * L + excl) * DD) + gi;
        #pragma unroll 4
        for (int f = 0; f < d; f++) __stcs(op + f * (DD / 4), v);
        return;
    }

    if (blk < SC + padBlocks) {
        // ---- padding: zero frames [total_b, L) of batch b ----
        const int pb = blk - SC;
        const int b = pb / bpb;
        const int pidx = pb - b * bpb;
        const int* drow = dur + b * SS;

        int s = 0;
        #pragma unroll
        for (int i = tid; i < SS; i += NT) s += drow[i];
        const int total = block_sum_384(s);

        const int warp = tid >> 5, lane = tid & 31;
        const float4 z = make_float4(0.f, 0.f, 0.f, 0.f);
        const int stride = bpb * 12;       // 12 warps per block
        for (int j = pidx * 12 + warp; j < L; j += stride) {
            if (j < total) continue;
            float4* op = reinterpret_cast<float4*>(out + ((size_t)b * L + j) * DD);
            __stcs(op + lane, z);
            __stcs(op + lane + 32, z);
            __stcs(op + lane + 64, z);
        }
        return;
    }

    // ---- tail: out_lengths per batch (as float) after the [B,L,D] tensor ----
    {
        float* tail = out + (size_t)BB * L * DD;
        const int warp = tid >> 5, lane = tid & 31;
        for (int b = warp; b < BB; b += 12) {
            const int* drow = dur + b * SS;
            int s = 0;
            #pragma unroll
            for (int i = lane; i < SS; i += 32) s += drow[i];
            #pragma unroll
            for (int off = 16; off; off >>= 1)
                s += __shfl_down_sync(0xffffffffu, s, off);
            if (lane == 0 && b < tail_n) tail[b] = (float)s;
        }
        for (int i = BB + tid; i < tail_n; i += NT) tail[i] = 0.f;
    }
}

extern "C" void kernel_launch(void* const* d_in, const int* in_sizes, int n_in,
                              void* d_out, int out_size) {
    // Identify inputs by element count, not order.
    const float* hidden;
    const int*   dur;
    if (in_sizes[0] == BB * SS) {
        dur    = (const int*)d_in[0];
        hidden = (const float*)d_in[1];
    } else {
        hidden = (const float*)d_in[0];
        dur    = (const int*)d_in[1];
    }
    float* out = (float*)d_out;

    const int frame = BB * DD;                 // 6144 floats per frame-slab
    const int L = out_size / frame;            // frames per batch
    const int tail_n = out_size - L * frame;   // 16 if lengths appended

    const int bpb = 4;                         // pad blocks per batch
    const int padBlocks = bpb * BB;            // 64

    const int grid = BB * SS / K + padBlocks + 1;
    fused_kernel<<<grid, NT>>>(hidden, dur, out, L, padBlocks, bpb, tail_n);
}